// round 1
// baseline (speedup 1.0000x reference)
#include <cuda_runtime.h>

// GARCH(1,1): h[t] = (omega + alpha*r[t-1]^2) + beta*h[t-1], h[0] = var(r, ddof=1)
// out[0..n)   = sqrt(h)
// out[n..2n)  = h
//
// Parallelization: beta < 1 makes the recurrence contractive; influence decays
// as beta^d (beta^256 ~ 8e-19, below fp32 ulp). Blocks process independent
// tiles with a 256-element halo. Within a block the recurrence is stitched
// EXACTLY via a Hillis-Steele scan with constant multipliers beta^(32*2^k).
// h0 only affects the first ~100 outputs -> computed by a deterministic
// two-kernel reduction and patched by a small fixup kernel.

#define TPB   256      // threads per block
#define CPT   32       // elements per thread (serial chunk)
#define TILE  (TPB*CPT)   // 8192 elements covered per block
#define HALO  256      // warm-up halo (first 8 threads' chunks; not written)
#define OPB   (TILE - HALO)  // 7936 outputs per block
#define FIXN  512      // prefix recomputed exactly by fixup kernel
#define MAXB  4096     // max blocks (partial-sum slots)

__device__ double g_psum[MAXB];
__device__ double g_psumsq[MAXB];

__device__ __forceinline__ int padidx(int k) { return k + (k >> 5); }

__global__ void __launch_bounds__(TPB)
garch_main(const float* __restrict__ r,
           const float* __restrict__ omega_p,
           const float* __restrict__ alpha_p,
           const float* __restrict__ beta_p,
           float* __restrict__ out,
           int n, int write_h)
{
    __shared__ float  bpad[TILE + TILE/32];   // padded: conflict-free both phases
    __shared__ float  sscan[TPB];
    __shared__ double wsum[TPB/32], wsq[TPB/32];

    const int   tid   = threadIdx.x;
    const float omega = *omega_p;
    const float alpha = *alpha_p;
    const float beta  = *beta_p;

    // tile covers t in [tile_t0, tile_t0 + TILE); outputs are k >= HALO
    const long long tile_t0 = (long long)blockIdx.x * OPB + 1 - HALO;

    double dsum = 0.0, dsq = 0.0;

    // ---- Phase 1: coalesced load, compute drivers b[t], variance partials ----
    #pragma unroll
    for (int it = 0; it < TILE / TPB; ++it) {
        int k = tid + it * TPB;
        long long t = tile_t0 + k;
        float b = 0.0f;
        if (t >= 1 && t < (long long)n) {
            float rv = r[t - 1];
            b = fmaf(alpha * rv, rv, omega);            // omega + alpha*r^2
            if (k >= HALO) {                            // exclusive region only
                dsum += (double)rv;
                dsq  += (double)rv * (double)rv;
            }
        }
        bpad[padidx(k)] = b;
    }
    // r[n-1] is never a driver but counts in the variance: add it once.
    if (blockIdx.x == 0 && tid == 0) {
        float rv = r[n - 1];
        dsum += (double)rv;
        dsq  += (double)rv * (double)rv;
    }
    __syncthreads();

    // ---- Phase 2: per-thread serial recurrence from zero state ----
    float p[CPT];
    {
        float h = 0.0f;
        const int base = padidx(tid * CPT);             // = tid*33, conflict-free
        #pragma unroll
        for (int j = 0; j < CPT; ++j) {
            h = fmaf(beta, h, bpad[base + j]);
            p[j] = h;
        }
        sscan[tid] = h;                                 // E_i = chunk end value
    }
    __syncthreads();

    // ---- Phase 3: exact block-level stitch: S_i = E_i + beta^32 * S_{i-1} ----
    float b2 = beta * beta, b4 = b2 * b2, b8 = b4 * b4, b16 = b8 * b8;
    float m = b16 * b16;                                // beta^32
    for (int d = 1; d < TPB; d <<= 1) {
        float v  = sscan[tid];
        float lo = (tid >= d) ? sscan[tid - d] : 0.0f;
        __syncthreads();
        v = fmaf(m, lo, v);
        sscan[tid] = v;
        __syncthreads();
        m *= m;                                         // beta^(32*2^step)
    }
    float carry = (tid >= 1) ? sscan[tid - 1] : 0.0f;   // h at chunk start - 1

    // ---- Phase 4: apply carry, stage h into shared ----
    {
        const int base = padidx(tid * CPT);
        float bp = beta;                                // beta^(j+1)
        #pragma unroll
        for (int j = 0; j < CPT; ++j) {
            float h = fmaf(bp, carry, p[j]);
            bpad[base + j] = h;
            bp *= beta;
        }
    }
    __syncthreads();

    // ---- Phase 5: coalesced stores of sqrt(h) and h ----
    #pragma unroll
    for (int it = 0; it < TILE / TPB; ++it) {
        int k = tid + it * TPB;
        if (k < HALO) continue;                         // halo: warm-up only
        long long t = tile_t0 + k;
        if (t < (long long)n) {
            float h = bpad[padidx(k)];
            out[t] = sqrtf(h);
            if (write_h) out[(long long)n + t] = h;
        }
    }

    // ---- Phase 6: deterministic variance block-reduce -> per-block slot ----
    unsigned mask = 0xFFFFFFFFu;
    #pragma unroll
    for (int off = 16; off; off >>= 1) {
        dsum += __shfl_down_sync(mask, dsum, off);
        dsq  += __shfl_down_sync(mask, dsq,  off);
    }
    const int wid = tid >> 5, lane = tid & 31;
    if (lane == 0) { wsum[wid] = dsum; wsq[wid] = dsq; }
    __syncthreads();
    if (tid == 0) {
        double a = 0.0, b_ = 0.0;
        #pragma unroll
        for (int w = 0; w < TPB / 32; ++w) { a += wsum[w]; b_ += wsq[w]; }
        g_psum[blockIdx.x]   = a;
        g_psumsq[blockIdx.x] = b_;
    }
}

__global__ void __launch_bounds__(TPB)
garch_fixup(const float* __restrict__ r,
            const float* __restrict__ omega_p,
            const float* __restrict__ alpha_p,
            const float* __restrict__ beta_p,
            float* __restrict__ out,
            int n, int nblocks, int write_h)
{
    __shared__ double red[TPB], red2[TPB];
    __shared__ float  rbuf[FIXN];
    __shared__ float  hbuf[FIXN];
    const int tid = threadIdx.x;

    // deterministic reduction of per-block partials
    double a = 0.0, b = 0.0;
    for (int i = tid; i < nblocks; i += TPB) { a += g_psum[i]; b += g_psumsq[i]; }
    red[tid] = a; red2[tid] = b;

    const int lim = (FIXN < n) ? FIXN : n;
    for (int i = tid; i < lim; i += TPB) rbuf[i] = r[i];
    __syncthreads();

    for (int s = TPB / 2; s; s >>= 1) {
        if (tid < s) { red[tid] += red[tid + s]; red2[tid] += red2[tid + s]; }
        __syncthreads();
    }

    if (tid == 0) {
        double S = red[0], Q = red2[0];
        double var = (Q - S * S / (double)n) / (double)(n - 1);
        float h0 = (float)var;
        float omega = *omega_p, alpha = *alpha_p, beta = *beta_p;
        float h = h0;
        hbuf[0] = h;
        for (int t = 1; t < lim; ++t) {
            float rv = rbuf[t - 1];
            h = fmaf(beta, h, fmaf(alpha * rv, rv, omega));
            hbuf[t] = h;
        }
    }
    __syncthreads();

    for (int t = tid; t < lim; t += TPB) {
        float h = hbuf[t];
        out[t] = sqrtf(h);
        if (write_h) out[(long long)n + t] = h;
    }
}

extern "C" void kernel_launch(void* const* d_in, const int* in_sizes, int n_in,
                              void* d_out, int out_size)
{
    const float* r  = (const float*)d_in[0];
    const float* om = (const float*)d_in[1];
    const float* al = (const float*)d_in[2];
    const float* be = (const float*)d_in[3];
    float* out = (float*)d_out;

    const int n = in_sizes[0];
    const int write_h = (out_size >= 2 * n) ? 1 : 0;

    int nblocks = (n - 1 + OPB - 1) / OPB;
    if (nblocks < 1)    nblocks = 1;
    if (nblocks > MAXB) nblocks = MAXB;

    garch_main <<<nblocks, TPB>>>(r, om, al, be, out, n, write_h);
    garch_fixup<<<1,       TPB>>>(r, om, al, be, out, n, nblocks, write_h);
}

// round 2
// speedup vs baseline: 4.8702x; 4.8702x over previous
#include <cuda_runtime.h>

// GARCH(1,1): h[t] = (omega + alpha*r[t-1]^2) + beta*h[t-1], h[0] = var(r, ddof=1)
// out[0..n) = sqrt(h), out[n..2n) = h
//
// beta < 1 => recurrence is contractive (beta^256 ~ 8e-19 < fp32 ulp): blocks
// process independent tiles with a 256-elem warm-up halo; intra-block stitch
// is EXACT (Hillis-Steele scan with multipliers beta^(32*2^k)). Main kernel
// computes the zero-initial-state solution h_hat; by linearity the true
// h[t] = h_hat[t] + beta^t * h0, which only matters for t < ~100, patched by
// a tiny fully-parallel fixup kernel. Variance partials are fp32 per-thread/
// warp (FP64 only at 8 values/block) to avoid B300's gimped FP64 pipe.

#define TPB   256
#define CPT   32
#define TILE  (TPB*CPT)        // 8192
#define HALO  256
#define OPB   (TILE - HALO)    // 7936
#define FIXN  256
#define MAXB  4096

__device__ double g_psum[MAXB];
__device__ double g_psumsq[MAXB];

__device__ __forceinline__ int padidx(int k) { return k + (k >> 5); }

__global__ void __launch_bounds__(TPB)
garch_main(const float* __restrict__ r,
           const float* __restrict__ omega_p,
           const float* __restrict__ alpha_p,
           const float* __restrict__ beta_p,
           float* __restrict__ out,
           int n, int write_h)
{
    __shared__ float  bpad[TILE + TILE/32];
    __shared__ float  sscan[TPB];
    __shared__ double wsum[TPB/32], wsq[TPB/32];

    const int   tid   = threadIdx.x;
    const float omega = *omega_p;
    const float alpha = *alpha_p;
    const float beta  = *beta_p;

    const long long tile_t0 = (long long)blockIdx.x * OPB + 1 - HALO;
    const long long s0      = tile_t0 - 1;              // r index for k=0

    float vs = 0.0f, vq = 0.0f;                          // fp32 variance partials

    // ---- Phase 1: load r, compute drivers b[t] = omega + alpha*r[t-1]^2 ----
    const bool interior = (s0 >= 0) && (s0 + TILE < (long long)n);
    if (interior) {
        const float4* __restrict__ r4 = (const float4*)(r + s0);   // 16B aligned
        #pragma unroll
        for (int it = 0; it < TILE / (4 * TPB); ++it) {
            int q = tid + it * TPB;
            float4 v = r4[q];
            int k = 4 * q;
            int base = padidx(k);                        // k%4==0: no pad break
            bpad[base + 0] = fmaf(alpha * v.x, v.x, omega);
            bpad[base + 1] = fmaf(alpha * v.y, v.y, omega);
            bpad[base + 2] = fmaf(alpha * v.z, v.z, omega);
            bpad[base + 3] = fmaf(alpha * v.w, v.w, omega);
            if (k >= HALO) {                             // exclusive region
                vs += (v.x + v.y) + (v.z + v.w);
                vq += fmaf(v.x, v.x, v.y * v.y) + fmaf(v.z, v.z, v.w * v.w);
            }
        }
    } else {
        #pragma unroll
        for (int it = 0; it < TILE / TPB; ++it) {
            int k = tid + it * TPB;
            long long t = tile_t0 + k;
            float b = 0.0f;
            if (t >= 1 && t < (long long)n) {
                float rv = r[t - 1];
                b = fmaf(alpha * rv, rv, omega);
                if (k >= HALO) { vs += rv; vq = fmaf(rv, rv, vq); }
            }
            bpad[padidx(k)] = b;
        }
    }
    if (blockIdx.x == 0 && tid == 0) {                   // r[n-1]: never a driver
        float rv = r[n - 1];
        vs += rv; vq = fmaf(rv, rv, vq);
    }
    __syncthreads();

    // ---- Phase 2: per-thread serial recurrence from zero state ----
    float p[CPT];
    {
        float h = 0.0f;
        const int base = padidx(tid * CPT);              // tid*33: conflict-free
        #pragma unroll
        for (int j = 0; j < CPT; ++j) {
            h = fmaf(beta, h, bpad[base + j]);
            p[j] = h;
        }
        sscan[tid] = h;
    }
    __syncthreads();

    // ---- Phase 3: exact stitch S_i = E_i + beta^32 * S_{i-1} ----
    float b2 = beta * beta, b4 = b2 * b2, b8 = b4 * b4, b16 = b8 * b8;
    float m = b16 * b16;                                 // beta^32
    for (int d = 1; d < TPB; d <<= 1) {
        float v  = sscan[tid];
        float lo = (tid >= d) ? sscan[tid - d] : 0.0f;
        __syncthreads();
        v = fmaf(m, lo, v);
        sscan[tid] = v;
        __syncthreads();
        m *= m;
    }
    float carry = (tid >= 1) ? sscan[tid - 1] : 0.0f;

    // ---- Phase 4: apply carry, stage h in shared ----
    {
        const int base = padidx(tid * CPT);
        float bp = beta;
        #pragma unroll
        for (int j = 0; j < CPT; ++j) {
            float h = fmaf(bp, carry, p[j]);
            bpad[base + j] = h;
            bp *= beta;
        }
    }
    __syncthreads();

    // ---- Phase 5: coalesced stores of sqrt(h) and h ----
    #pragma unroll
    for (int it = 0; it < TILE / TPB; ++it) {
        int k = tid + it * TPB;
        if (k < HALO) continue;
        long long t = tile_t0 + k;
        if (t < (long long)n) {
            float h = bpad[padidx(k)];
            out[t] = sqrtf(h);
            if (write_h) out[(long long)n + t] = h;
        }
    }

    // ---- Phase 6: deterministic variance reduce (fp32 -> fp64 at warp level) ----
    unsigned mask = 0xFFFFFFFFu;
    #pragma unroll
    for (int off = 16; off; off >>= 1) {
        vs += __shfl_down_sync(mask, vs, off);
        vq += __shfl_down_sync(mask, vq, off);
    }
    const int wid = tid >> 5, lane = tid & 31;
    if (lane == 0) { wsum[wid] = (double)vs; wsq[wid] = (double)vq; }
    __syncthreads();
    if (tid == 0) {
        double a = 0.0, b_ = 0.0;
        #pragma unroll
        for (int w = 0; w < TPB / 32; ++w) { a += wsum[w]; b_ += wsq[w]; }
        g_psum[blockIdx.x]   = a;
        g_psumsq[blockIdx.x] = b_;
    }
}

__global__ void __launch_bounds__(TPB)
garch_fixup(const float* __restrict__ r,
            const float* __restrict__ omega_p,
            const float* __restrict__ alpha_p,
            const float* __restrict__ beta_p,
            float* __restrict__ out,
            int n, int nblocks, int write_h)
{
    __shared__ double red[TPB], red2[TPB];
    __shared__ float  sh0;
    const int tid = threadIdx.x;

    double a = 0.0, b = 0.0;
    for (int i = tid; i < nblocks; i += TPB) { a += g_psum[i]; b += g_psumsq[i]; }
    red[tid] = a; red2[tid] = b;
    __syncthreads();
    for (int s = TPB / 2; s; s >>= 1) {
        if (tid < s) { red[tid] += red[tid + s]; red2[tid] += red2[tid + s]; }
        __syncthreads();
    }
    if (tid == 0) {
        double S = red[0], Q = red2[0];
        sh0 = (float)((Q - S * S / (double)n) / (double)(n - 1));
    }
    __syncthreads();

    const float h0   = sh0;
    const float beta = *beta_p;
    const int   lim  = (FIXN < n) ? FIXN : n;

    if (write_h) {
        // h[t] = h_hat[t] + beta^t * h0 (linearity); h_hat already in out[n+t].
        for (int t = tid; t < lim; t += TPB) {
            float bp = 1.0f, base = beta;
            int e = t;
            while (e) { if (e & 1) bp *= base; base *= base; e >>= 1; }
            float hh = (t == 0) ? h0 : fmaf(bp, h0, out[(long long)n + t]);
            out[(long long)n + t] = hh;
            out[t] = sqrtf(hh);
        }
    } else {
        // rare fallback: serial exact prefix
        if (tid == 0) {
            float omega = *omega_p, alpha = *alpha_p;
            float h = h0;
            out[0] = sqrtf(h);
            for (int t = 1; t < lim; ++t) {
                float rv = r[t - 1];
                h = fmaf(beta, h, fmaf(alpha * rv, rv, omega));
                out[t] = sqrtf(h);
            }
        }
    }
}

extern "C" void kernel_launch(void* const* d_in, const int* in_sizes, int n_in,
                              void* d_out, int out_size)
{
    const float* r  = (const float*)d_in[0];
    const float* om = (const float*)d_in[1];
    const float* al = (const float*)d_in[2];
    const float* be = (const float*)d_in[3];
    float* out = (float*)d_out;

    const int n = in_sizes[0];
    const int write_h = (out_size >= 2 * n) ? 1 : 0;

    int nblocks = (n - 1 + OPB - 1) / OPB;
    if (nblocks < 1)    nblocks = 1;
    if (nblocks > MAXB) nblocks = MAXB;

    garch_main <<<nblocks, TPB>>>(r, om, al, be, out, n, write_h);
    garch_fixup<<<1,       TPB>>>(r, om, al, be, out, n, nblocks, write_h);
}